// round 6
// baseline (speedup 1.0000x reference)
#include <cuda_runtime.h>

// Problem constants
#define Nn   100000
#define Ee   800000
#define Gg   4096
#define INF  143
#define Hh   128
#define BN_INV 0.9999950000374997f   // rsqrt(1 + 1e-5)

// ---------------------------------------------------------------------------
// Device scratch (no allocations allowed in kernel_launch)
// ---------------------------------------------------------------------------
__device__ __align__(16) float g_h[Nn * Hh];     // g = dis * (h @ W), per layer
__device__ __align__(16) float g_act[Nn * Hh];   // post BN+ReLU activations
__device__ float g_dis[Nn];                      // deg^{-1/2}
__device__ int   g_deg[Nn];
__device__ int   g_rowptr[Nn + 1];
__device__ int   g_fill[Nn];
__device__ int   g_col[Ee];                      // src indices grouped by dst
__device__ __align__(16) float g_pool[Gg * Hh];
__device__ float g_cnt[Gg];
__device__ int   g_is64;                         // index dtype flag (1 = int64)

// ---------------------------------------------------------------------------
// Dtype sniff: int64 little-endian values < 2^31 have zero high words at all
// odd 32-bit positions; int32 node indices are random in [0, N) so 256 odd
// words being all zero is impossible in practice.
// ---------------------------------------------------------------------------
__global__ void k_sniff(const int* __restrict__ ei32) {
    __shared__ int ok;
    if (threadIdx.x == 0) ok = 1;
    __syncthreads();
    if (ei32[2 * threadIdx.x + 1] != 0) ok = 0;
    __syncthreads();
    if (threadIdx.x == 0) g_is64 = ok;
}

__device__ __forceinline__ int load_idx(const void* p, long long i) {
    return g_is64 ? (int)((const long long*)p)[i] : ((const int*)p)[i];
}

// ---------------------------------------------------------------------------
// Zero all per-call scratch
// ---------------------------------------------------------------------------
__global__ void k_zero() {
    int i = blockIdx.x * blockDim.x + threadIdx.x;
    int stride = gridDim.x * blockDim.x;
    for (int j = i; j < Nn; j += stride) { g_deg[j] = 0; g_fill[j] = 0; }
    for (int j = i; j < Gg * Hh; j += stride) g_pool[j] = 0.f;
    for (int j = i; j < Gg; j += stride) g_cnt[j] = 0.f;
}

// ---------------------------------------------------------------------------
// In-degree histogram over dst
// ---------------------------------------------------------------------------
__global__ void k_deg(const void* __restrict__ ei) {
    int e = blockIdx.x * blockDim.x + threadIdx.x;
    if (e < Ee) atomicAdd(&g_deg[load_idx(ei, (long long)Ee + e)], 1);
}

// ---------------------------------------------------------------------------
// Single-block chunked exclusive scan: deg -> rowptr; also dis = rsqrt(deg+1)
// ---------------------------------------------------------------------------
__global__ void k_scan() {
    __shared__ int warpsums[32];
    __shared__ int s_carry;
    int tid = threadIdx.x;
    int lane = tid & 31, wid = tid >> 5;
    if (tid == 0) s_carry = 0;
    __syncthreads();
    for (int base = 0; base < Nn; base += 1024) {
        int i = base + tid;
        int v = (i < Nn) ? g_deg[i] : 0;
        int incl = v;
        #pragma unroll
        for (int o = 1; o < 32; o <<= 1) {
            int t = __shfl_up_sync(0xFFFFFFFFu, incl, o);
            if (lane >= o) incl += t;
        }
        if (lane == 31) warpsums[wid] = incl;
        __syncthreads();
        if (tid < 32) {
            int w = warpsums[tid];
            int winc = w;
            #pragma unroll
            for (int o = 1; o < 32; o <<= 1) {
                int t = __shfl_up_sync(0xFFFFFFFFu, winc, o);
                if (tid >= o) winc += t;
            }
            warpsums[tid] = winc - w;   // exclusive warp offsets
        }
        __syncthreads();
        if (i < Nn) {
            g_rowptr[i] = s_carry + warpsums[wid] + (incl - v);
            g_dis[i] = rsqrtf((float)v + 1.0f);
        }
        __syncthreads();
        if (tid == 1023) s_carry += warpsums[31] + incl;  // chunk total
        __syncthreads();
    }
    if (tid == 0) g_rowptr[Nn] = Ee;
}

// ---------------------------------------------------------------------------
// Scatter edges into CSR slots (order within a node is arbitrary; fp sums
// stay well inside the 1e-3 tolerance)
// ---------------------------------------------------------------------------
__global__ void k_fill(const void* __restrict__ ei) {
    int e = blockIdx.x * blockDim.x + threadIdx.x;
    if (e < Ee) {
        int s = load_idx(ei, e);
        int d = load_idx(ei, (long long)Ee + e);
        int pos = g_rowptr[d] + atomicAdd(&g_fill[d], 1);
        g_col[pos] = s;
    }
}

// ---------------------------------------------------------------------------
// GEMM: g_h[row, :] = dis[row] * (in[row, :] @ W)     (W is [K,128] row-major)
// Block tile 64 rows x 128 cols, 256 threads, 4x8 per-thread register tile.
// in == nullptr means "read g_act".
// ---------------------------------------------------------------------------
__global__ __launch_bounds__(256) void k_gemm(const float* __restrict__ in,
                                              int lda, int K,
                                              const float* __restrict__ W) {
    __shared__ __align__(16) float xs[64 * 17];   // [m][kk], padded stride 17
    __shared__ __align__(16) float ws[16 * 128];  // [kk][n]
    const float* src = in ? in : g_act;

    int tid = threadIdx.x;
    int tx = tid & 15, ty = tid >> 4;
    int m0 = blockIdx.x * 64;

    float acc[4][8];
    #pragma unroll
    for (int r = 0; r < 4; r++)
        #pragma unroll
        for (int j = 0; j < 8; j++) acc[r][j] = 0.f;

    for (int k0 = 0; k0 < K; k0 += 16) {
        #pragma unroll
        for (int t = 0; t < 4; t++) {            // 1024 x-tile elems
            int idx = t * 256 + tid;
            int kk = idx & 15, m = idx >> 4;
            int row = m0 + m, kg = k0 + kk;
            xs[m * 17 + kk] = (row < Nn && kg < K) ? src[(long long)row * lda + kg] : 0.f;
        }
        #pragma unroll
        for (int t = 0; t < 8; t++) {            // 2048 w-tile elems
            int idx = t * 256 + tid;
            int n = idx & 127, kk = idx >> 7;
            int kg = k0 + kk;
            ws[kk * 128 + n] = (kg < K) ? W[kg * 128 + n] : 0.f;
        }
        __syncthreads();

        const float4* ws4 = reinterpret_cast<const float4*>(ws);
        #pragma unroll
        for (int kk = 0; kk < 16; kk++) {
            float4 wA = ws4[kk * 32 + tx];        // cols tx*4 .. +3
            float4 wB = ws4[kk * 32 + 16 + tx];   // cols 64+tx*4 .. +3
            #pragma unroll
            for (int r = 0; r < 4; r++) {
                float xv = xs[(ty * 4 + r) * 17 + kk];
                acc[r][0] = fmaf(xv, wA.x, acc[r][0]);
                acc[r][1] = fmaf(xv, wA.y, acc[r][1]);
                acc[r][2] = fmaf(xv, wA.z, acc[r][2]);
                acc[r][3] = fmaf(xv, wA.w, acc[r][3]);
                acc[r][4] = fmaf(xv, wB.x, acc[r][4]);
                acc[r][5] = fmaf(xv, wB.y, acc[r][5]);
                acc[r][6] = fmaf(xv, wB.z, acc[r][6]);
                acc[r][7] = fmaf(xv, wB.w, acc[r][7]);
            }
        }
        __syncthreads();
    }

    #pragma unroll
    for (int r = 0; r < 4; r++) {
        int row = m0 + ty * 4 + r;
        if (row < Nn) {
            float s = g_dis[row];
            float4 o0, o1;
            o0.x = acc[r][0] * s; o0.y = acc[r][1] * s;
            o0.z = acc[r][2] * s; o0.w = acc[r][3] * s;
            o1.x = acc[r][4] * s; o1.y = acc[r][5] * s;
            o1.z = acc[r][6] * s; o1.w = acc[r][7] * s;
            reinterpret_cast<float4*>(g_h + (long long)row * Hh)[tx] = o0;
            reinterpret_cast<float4*>(g_h + (long long)row * Hh + 64)[tx] = o1;
        }
    }
}

// ---------------------------------------------------------------------------
// Aggregation + bias + BN(eval) + ReLU:
//   g_act[i] = relu(gamma*BN_INV*(dis[i]*(g[i] + sum_{src in in(i)} g[src]) + b) + beta)
// One warp per node, float4 per lane (32 lanes x 4 = 128 cols).
// ---------------------------------------------------------------------------
__global__ __launch_bounds__(128) void k_agg(const float* __restrict__ bias,
                                             const float* __restrict__ gamma,
                                             const float* __restrict__ beta) {
    int warp = threadIdx.x >> 5, lane = threadIdx.x & 31;
    int node = blockIdx.x * 4 + warp;
    if (node >= Nn) return;

    const float4* h4 = reinterpret_cast<const float4*>(g_h);
    int r0 = g_rowptr[node], r1 = g_rowptr[node + 1];

    float4 a = h4[(long long)node * 32 + lane];   // self term (already dis-scaled)
    int e = r0;
    for (; e + 4 <= r1; e += 4) {                 // 4-deep MLP over edges
        int s0 = g_col[e], s1 = g_col[e + 1], s2 = g_col[e + 2], s3 = g_col[e + 3];
        float4 v0 = h4[(long long)s0 * 32 + lane];
        float4 v1 = h4[(long long)s1 * 32 + lane];
        float4 v2 = h4[(long long)s2 * 32 + lane];
        float4 v3 = h4[(long long)s3 * 32 + lane];
        a.x += (v0.x + v1.x) + (v2.x + v3.x);
        a.y += (v0.y + v1.y) + (v2.y + v3.y);
        a.z += (v0.z + v1.z) + (v2.z + v3.z);
        a.w += (v0.w + v1.w) + (v2.w + v3.w);
    }
    for (; e < r1; e++) {
        float4 v = h4[(long long)g_col[e] * 32 + lane];
        a.x += v.x; a.y += v.y; a.z += v.z; a.w += v.w;
    }

    float d = g_dis[node];
    float4 bb = reinterpret_cast<const float4*>(bias)[lane];
    float4 gm = reinterpret_cast<const float4*>(gamma)[lane];
    float4 bt = reinterpret_cast<const float4*>(beta)[lane];
    float4 o;
    o.x = fmaxf(fmaf(gm.x * BN_INV, fmaf(d, a.x, bb.x), bt.x), 0.f);
    o.y = fmaxf(fmaf(gm.y * BN_INV, fmaf(d, a.y, bb.y), bt.y), 0.f);
    o.z = fmaxf(fmaf(gm.z * BN_INV, fmaf(d, a.z, bb.z), bt.z), 0.f);
    o.w = fmaxf(fmaf(gm.w * BN_INV, fmaf(d, a.w, bb.w), bt.w), 0.f);
    reinterpret_cast<float4*>(g_act)[(long long)node * 32 + lane] = o;
}

// ---------------------------------------------------------------------------
// Global mean pool: atomic accumulate sums + counts per graph
// ---------------------------------------------------------------------------
__global__ __launch_bounds__(128) void k_pool(const void* __restrict__ batch) {
    int node = blockIdx.x;
    int c = threadIdx.x;
    int g = load_idx(batch, node);
    atomicAdd(&g_pool[g * Hh + c], g_act[(long long)node * Hh + c]);
    if (c == 0) atomicAdd(&g_cnt[g], 1.f);
}

// ---------------------------------------------------------------------------
// Head: mean -> relu(mean@wc1 + bc1) -> @wc2 + bc2. One 64-thread block/graph.
// ---------------------------------------------------------------------------
__global__ __launch_bounds__(64) void k_head(const float* __restrict__ wc1,
                                             const float* __restrict__ bc1,
                                             const float* __restrict__ wc2,
                                             const float* __restrict__ bc2,
                                             float* __restrict__ out) {
    __shared__ float mean[128];
    __shared__ float part[2];
    int g = blockIdx.x, t = threadIdx.x;
    float inv = 1.f / fmaxf(g_cnt[g], 1.f);
    mean[t]      = g_pool[g * Hh + t] * inv;
    mean[t + 64] = g_pool[g * Hh + 64 + t] * inv;
    __syncthreads();

    float z = bc1[t];
    #pragma unroll 8
    for (int k = 0; k < 128; k++)
        z = fmaf(mean[k], wc1[k * 64 + t], z);
    z = fmaxf(z, 0.f) * wc2[t];

    #pragma unroll
    for (int o = 16; o; o >>= 1) z += __shfl_down_sync(0xFFFFFFFFu, z, o);
    if ((t & 31) == 0) part[t >> 5] = z;
    __syncthreads();
    if (t == 0) out[g] = part[0] + part[1] + bc2[0];
}

// ---------------------------------------------------------------------------
// Launch
// ---------------------------------------------------------------------------
extern "C" void kernel_launch(void* const* d_in, const int* in_sizes, int n_in,
                              void* d_out, int out_size) {
    const float* x      = (const float*)d_in[0];
    const void*  ei     = d_in[1];
    const void*  batch  = d_in[2];
    const float* w0     = (const float*)d_in[3];
    const float* b0     = (const float*)d_in[4];
    const float* ws     = (const float*)d_in[5];
    const float* bs     = (const float*)d_in[6];
    const float* gammas = (const float*)d_in[7];
    const float* betas  = (const float*)d_in[8];
    const float* wc1    = (const float*)d_in[9];
    const float* bc1    = (const float*)d_in[10];
    const float* wc2    = (const float*)d_in[11];
    const float* bc2    = (const float*)d_in[12];
    float* out = (float*)d_out;

    k_sniff<<<1, 256>>>((const int*)ei);
    k_zero<<<1024, 256>>>();
    k_deg<<<(Ee + 255) / 256, 256>>>(ei);
    k_scan<<<1, 1024>>>();
    k_fill<<<(Ee + 255) / 256, 256>>>(ei);

    const int gemm_grid = (Nn + 63) / 64;
    const int agg_grid  = (Nn + 3) / 4;
    for (int l = 0; l < 4; l++) {
        if (l == 0)
            k_gemm<<<gemm_grid, 256>>>(x, INF, INF, w0);
        else
            k_gemm<<<gemm_grid, 256>>>(nullptr, Hh, Hh, ws + (size_t)(l - 1) * Hh * Hh);
        const float* bias = (l == 0) ? b0 : bs + (size_t)(l - 1) * Hh;
        k_agg<<<agg_grid, 128>>>(bias, gammas + (size_t)l * Hh, betas + (size_t)l * Hh);
    }

    k_pool<<<Nn, 128>>>(batch);
    k_head<<<Gg, 64>>>(wc1, bc1, wc2, bc2, out);
}

// round 7
// speedup vs baseline: 1.1221x; 1.1221x over previous
#include <cuda_runtime.h>

// Problem constants
#define Nn   100000
#define Ee   800000
#define Gg   4096
#define INF  143
#define Hh   128
#define BN_INV 0.9999950000374997f   // rsqrt(1 + 1e-5)
#define NBLK ((Nn + 1023) / 1024)    // 98 scan blocks

typedef unsigned long long u64;

// ---------------------------------------------------------------------------
// Device scratch (no allocations allowed in kernel_launch)
// ---------------------------------------------------------------------------
__device__ __align__(16) float g_h[Nn * Hh];     // g = dis * (h @ W), per layer
__device__ __align__(16) float g_act[Nn * Hh];   // post BN+ReLU activations
__device__ float g_dis[Nn];                      // deg^{-1/2}
__device__ int   g_deg[Nn];
__device__ int   g_rowptr[Nn + 1];
__device__ int   g_fill[Nn];
__device__ int   g_col[Ee];                      // src indices grouped by dst
__device__ __align__(16) float g_pool[Gg * Hh];
__device__ float g_cnt[Gg];
__device__ int   g_is64;                         // index dtype flag (1 = int64)
__device__ int   g_bsum[NBLK];                   // scan block sums

// ---------------------------------------------------------------------------
// f32x2 helpers (Blackwell packed fp32; ptxas will not auto-fuse)
// ---------------------------------------------------------------------------
__device__ __forceinline__ u64 fma2(u64 a, u64 b, u64 c) {
    u64 d;
    asm("fma.rn.f32x2 %0, %1, %2, %3;" : "=l"(d) : "l"(a), "l"(b), "l"(c));
    return d;
}
__device__ __forceinline__ u64 dup2(float v) {
    u64 p;
    asm("mov.b64 %0, {%1, %1};" : "=l"(p) : "f"(v));
    return p;
}
__device__ __forceinline__ float2 unpack2(u64 a) {
    float2 f;
    asm("mov.b64 {%0, %1}, %2;" : "=f"(f.x), "=f"(f.y) : "l"(a));
    return f;
}

// ---------------------------------------------------------------------------
// Dtype sniff: int64 little-endian values < 2^31 have zero high words at all
// odd 32-bit positions; int32 node indices are random in [0, N) so 256 odd
// words being all zero is impossible in practice.
// ---------------------------------------------------------------------------
__global__ void k_sniff(const int* __restrict__ ei32) {
    __shared__ int ok;
    if (threadIdx.x == 0) ok = 1;
    __syncthreads();
    if (ei32[2 * threadIdx.x + 1] != 0) ok = 0;
    __syncthreads();
    if (threadIdx.x == 0) g_is64 = ok;
}

__device__ __forceinline__ int load_idx(const void* p, long long i) {
    return g_is64 ? (int)((const long long*)p)[i] : ((const int*)p)[i];
}

// ---------------------------------------------------------------------------
// Zero all per-call scratch
// ---------------------------------------------------------------------------
__global__ void k_zero() {
    int i = blockIdx.x * blockDim.x + threadIdx.x;
    int stride = gridDim.x * blockDim.x;
    for (int j = i; j < Nn; j += stride) { g_deg[j] = 0; g_fill[j] = 0; }
    for (int j = i; j < Gg * Hh; j += stride) g_pool[j] = 0.f;
    for (int j = i; j < Gg; j += stride) g_cnt[j] = 0.f;
}

// ---------------------------------------------------------------------------
// In-degree histogram over dst
// ---------------------------------------------------------------------------
__global__ void k_deg(const void* __restrict__ ei) {
    int e = blockIdx.x * blockDim.x + threadIdx.x;
    if (e < Ee) atomicAdd(&g_deg[load_idx(ei, (long long)Ee + e)], 1);
}

// ---------------------------------------------------------------------------
// Multi-block exclusive scan of g_deg -> g_rowptr (3 kernels)
// ---------------------------------------------------------------------------
__global__ __launch_bounds__(1024) void k_scan1() {   // block sums
    __shared__ int wsum[32];
    int i = blockIdx.x * 1024 + threadIdx.x;
    int lane = threadIdx.x & 31, wid = threadIdx.x >> 5;
    int v = (i < Nn) ? g_deg[i] : 0;
    #pragma unroll
    for (int o = 16; o; o >>= 1) v += __shfl_down_sync(0xFFFFFFFFu, v, o);
    if (lane == 0) wsum[wid] = v;
    __syncthreads();
    if (wid == 0) {
        int s = wsum[lane];
        #pragma unroll
        for (int o = 16; o; o >>= 1) s += __shfl_down_sync(0xFFFFFFFFu, s, o);
        if (lane == 0) g_bsum[blockIdx.x] = s;
    }
}

__global__ __launch_bounds__(128) void k_scan2() {    // scan 98 block sums
    __shared__ int wsum[4];
    int tid = threadIdx.x, lane = tid & 31, wid = tid >> 5;
    int v = (tid < NBLK) ? g_bsum[tid] : 0;
    int incl = v;
    #pragma unroll
    for (int o = 1; o < 32; o <<= 1) {
        int t = __shfl_up_sync(0xFFFFFFFFu, incl, o);
        if (lane >= o) incl += t;
    }
    if (lane == 31) wsum[wid] = incl;
    __syncthreads();
    int off = 0;
    #pragma unroll
    for (int w = 0; w < 4; w++) if (w < wid) off += wsum[w];
    if (tid < NBLK) g_bsum[tid] = off + incl - v;     // exclusive
    if (tid == 0) g_rowptr[Nn] = Ee;
}

__global__ __launch_bounds__(1024) void k_scan3() {   // local scan + offset
    __shared__ int wsum[32];
    int i = blockIdx.x * 1024 + threadIdx.x;
    int lane = threadIdx.x & 31, wid = threadIdx.x >> 5;
    int v = (i < Nn) ? g_deg[i] : 0;
    int incl = v;
    #pragma unroll
    for (int o = 1; o < 32; o <<= 1) {
        int t = __shfl_up_sync(0xFFFFFFFFu, incl, o);
        if (lane >= o) incl += t;
    }
    if (lane == 31) wsum[wid] = incl;
    __syncthreads();
    if (wid == 0) {
        int w = wsum[lane];
        int winc = w;
        #pragma unroll
        for (int o = 1; o < 32; o <<= 1) {
            int t = __shfl_up_sync(0xFFFFFFFFu, winc, o);
            if (lane >= o) winc += t;
        }
        wsum[lane] = winc - w;
    }
    __syncthreads();
    if (i < Nn) {
        g_rowptr[i] = g_bsum[blockIdx.x] + wsum[wid] + (incl - v);
        g_dis[i] = rsqrtf((float)v + 1.0f);
    }
}

// ---------------------------------------------------------------------------
// Scatter edges into CSR slots
// ---------------------------------------------------------------------------
__global__ void k_fill(const void* __restrict__ ei) {
    int e = blockIdx.x * blockDim.x + threadIdx.x;
    if (e < Ee) {
        int s = load_idx(ei, e);
        int d = load_idx(ei, (long long)Ee + e);
        int pos = g_rowptr[d] + atomicAdd(&g_fill[d], 1);
        g_col[pos] = s;
    }
}

// ---------------------------------------------------------------------------
// GEMM: g_h[row,:] = dis[row] * (in[row,:] @ W), W is [K,128] row-major.
// 64x128 block tile, 256 threads, 4x8 per-thread tile computed as 4x4 f32x2
// packed accumulators. x is stored pre-duplicated (v,v) in smem so the inner
// loop has zero packing movs; W pairs come from type-punned float4 LDS.128.
// in == nullptr means "read g_act".
// ---------------------------------------------------------------------------
__global__ __launch_bounds__(256) void k_gemm(const float* __restrict__ in,
                                              int lda, int K,
                                              const float* __restrict__ W) {
    __shared__ __align__(16) u64 xs2[64 * 18];    // [m][kk] duplicated pairs
    __shared__ __align__(16) float ws[16 * 128];  // [kk][n]
    const float* src = in ? in : g_act;

    int tid = threadIdx.x;
    int tx = tid & 15, ty = tid >> 4;
    int m0 = blockIdx.x * 64;

    u64 acc[4][4];
    #pragma unroll
    for (int r = 0; r < 4; r++)
        #pragma unroll
        for (int j = 0; j < 4; j++) acc[r][j] = 0ull;  // (0.f, 0.f)

    for (int k0 = 0; k0 < K; k0 += 16) {
        #pragma unroll
        for (int t = 0; t < 4; t++) {            // 1024 x-tile elems
            int idx = t * 256 + tid;
            int kk = idx & 15, m = idx >> 4;
            int row = m0 + m, kg = k0 + kk;
            float v = (row < Nn && kg < K) ? src[(long long)row * lda + kg] : 0.f;
            xs2[m * 18 + kk] = dup2(v);
        }
        #pragma unroll
        for (int t = 0; t < 8; t++) {            // 2048 w-tile elems
            int idx = t * 256 + tid;
            int n = idx & 127, kk = idx >> 7;
            int kg = k0 + kk;
            ws[kk * 128 + n] = (kg < K) ? W[kg * 128 + n] : 0.f;
        }
        __syncthreads();

        #pragma unroll
        for (int kk = 0; kk < 16; kk++) {
            // cols tx*4..+3 and 64+tx*4..+3, as (lo,hi) f32 pairs
            ulonglong2 wA = *reinterpret_cast<const ulonglong2*>(&ws[kk * 128 + tx * 4]);
            ulonglong2 wB = *reinterpret_cast<const ulonglong2*>(&ws[kk * 128 + 64 + tx * 4]);
            #pragma unroll
            for (int r = 0; r < 4; r++) {
                u64 xx = xs2[(ty * 4 + r) * 18 + kk];
                acc[r][0] = fma2(xx, wA.x, acc[r][0]);
                acc[r][1] = fma2(xx, wA.y, acc[r][1]);
                acc[r][2] = fma2(xx, wB.x, acc[r][2]);
                acc[r][3] = fma2(xx, wB.y, acc[r][3]);
            }
        }
        __syncthreads();
    }

    #pragma unroll
    for (int r = 0; r < 4; r++) {
        int row = m0 + ty * 4 + r;
        if (row < Nn) {
            float s = g_dis[row];
            float2 p0 = unpack2(acc[r][0]), p1 = unpack2(acc[r][1]);
            float2 p2 = unpack2(acc[r][2]), p3 = unpack2(acc[r][3]);
            float4 o0 = make_float4(p0.x * s, p0.y * s, p1.x * s, p1.y * s);
            float4 o1 = make_float4(p2.x * s, p2.y * s, p3.x * s, p3.y * s);
            reinterpret_cast<float4*>(g_h + (long long)row * Hh)[tx] = o0;
            reinterpret_cast<float4*>(g_h + (long long)row * Hh + 64)[tx] = o1;
        }
    }
}

// ---------------------------------------------------------------------------
// Aggregation + bias + BN(eval) + ReLU (one warp per node, float4 per lane)
// ---------------------------------------------------------------------------
__global__ __launch_bounds__(128) void k_agg(const float* __restrict__ bias,
                                             const float* __restrict__ gamma,
                                             const float* __restrict__ beta) {
    int warp = threadIdx.x >> 5, lane = threadIdx.x & 31;
    int node = blockIdx.x * 4 + warp;
    if (node >= Nn) return;

    const float4* h4 = reinterpret_cast<const float4*>(g_h);
    int r0 = g_rowptr[node], r1 = g_rowptr[node + 1];

    float4 a = h4[(long long)node * 32 + lane];   // self term (dis-prescaled)
    int e = r0;
    for (; e + 4 <= r1; e += 4) {
        int s0 = g_col[e], s1 = g_col[e + 1], s2 = g_col[e + 2], s3 = g_col[e + 3];
        float4 v0 = h4[(long long)s0 * 32 + lane];
        float4 v1 = h4[(long long)s1 * 32 + lane];
        float4 v2 = h4[(long long)s2 * 32 + lane];
        float4 v3 = h4[(long long)s3 * 32 + lane];
        a.x += (v0.x + v1.x) + (v2.x + v3.x);
        a.y += (v0.y + v1.y) + (v2.y + v3.y);
        a.z += (v0.z + v1.z) + (v2.z + v3.z);
        a.w += (v0.w + v1.w) + (v2.w + v3.w);
    }
    for (; e < r1; e++) {
        float4 v = h4[(long long)g_col[e] * 32 + lane];
        a.x += v.x; a.y += v.y; a.z += v.z; a.w += v.w;
    }

    float d = g_dis[node];
    float4 bb = reinterpret_cast<const float4*>(bias)[lane];
    float4 gm = reinterpret_cast<const float4*>(gamma)[lane];
    float4 bt = reinterpret_cast<const float4*>(beta)[lane];
    float4 o;
    o.x = fmaxf(fmaf(gm.x * BN_INV, fmaf(d, a.x, bb.x), bt.x), 0.f);
    o.y = fmaxf(fmaf(gm.y * BN_INV, fmaf(d, a.y, bb.y), bt.y), 0.f);
    o.z = fmaxf(fmaf(gm.z * BN_INV, fmaf(d, a.z, bb.z), bt.z), 0.f);
    o.w = fmaxf(fmaf(gm.w * BN_INV, fmaf(d, a.w, bb.w), bt.w), 0.f);
    reinterpret_cast<float4*>(g_act)[(long long)node * 32 + lane] = o;
}

// ---------------------------------------------------------------------------
// Global mean pool, segmented: batch is sorted, so a warp walks 32 consecutive
// node rows accumulating in registers and flushes atomics only on graph change
// (~24 nodes/graph -> ~13x fewer atomics than per-node).
// ---------------------------------------------------------------------------
__global__ __launch_bounds__(128) void k_pool(const void* __restrict__ batch) {
    int warp = threadIdx.x >> 5, lane = threadIdx.x & 31;
    int base = (blockIdx.x * 4 + warp) * 32;
    if (base >= Nn) return;
    int end = base + 32 < Nn ? base + 32 : Nn;

    const float4* a4 = reinterpret_cast<const float4*>(g_act);
    float4 acc = make_float4(0.f, 0.f, 0.f, 0.f);
    int cur = load_idx(batch, base);
    int cnt = 0;

    for (int n = base; n < end; n++) {
        int g = load_idx(batch, n);
        if (g != cur) {
            float* dst = &g_pool[cur * Hh + lane * 4];
            atomicAdd(dst + 0, acc.x); atomicAdd(dst + 1, acc.y);
            atomicAdd(dst + 2, acc.z); atomicAdd(dst + 3, acc.w);
            if (lane == 0) atomicAdd(&g_cnt[cur], (float)cnt);
            acc = make_float4(0.f, 0.f, 0.f, 0.f);
            cnt = 0; cur = g;
        }
        float4 v = a4[(long long)n * 32 + lane];
        acc.x += v.x; acc.y += v.y; acc.z += v.z; acc.w += v.w;
        cnt++;
    }
    float* dst = &g_pool[cur * Hh + lane * 4];
    atomicAdd(dst + 0, acc.x); atomicAdd(dst + 1, acc.y);
    atomicAdd(dst + 2, acc.z); atomicAdd(dst + 3, acc.w);
    if (lane == 0) atomicAdd(&g_cnt[cur], (float)cnt);
}

// ---------------------------------------------------------------------------
// Head: mean -> relu(mean@wc1 + bc1) -> @wc2 + bc2. One 64-thread block/graph.
// ---------------------------------------------------------------------------
__global__ __launch_bounds__(64) void k_head(const float* __restrict__ wc1,
                                             const float* __restrict__ bc1,
                                             const float* __restrict__ wc2,
                                             const float* __restrict__ bc2,
                                             float* __restrict__ out) {
    __shared__ float mean[128];
    __shared__ float part[2];
    int g = blockIdx.x, t = threadIdx.x;
    float inv = 1.f / fmaxf(g_cnt[g], 1.f);
    mean[t]      = g_pool[g * Hh + t] * inv;
    mean[t + 64] = g_pool[g * Hh + 64 + t] * inv;
    __syncthreads();

    float z = bc1[t];
    #pragma unroll 8
    for (int k = 0; k < 128; k++)
        z = fmaf(mean[k], wc1[k * 64 + t], z);
    z = fmaxf(z, 0.f) * wc2[t];

    #pragma unroll
    for (int o = 16; o; o >>= 1) z += __shfl_down_sync(0xFFFFFFFFu, z, o);
    if ((t & 31) == 0) part[t >> 5] = z;
    __syncthreads();
    if (t == 0) out[g] = part[0] + part[1] + bc2[0];
}

// ---------------------------------------------------------------------------
// Launch
// ---------------------------------------------------------------------------
extern "C" void kernel_launch(void* const* d_in, const int* in_sizes, int n_in,
                              void* d_out, int out_size) {
    const float* x      = (const float*)d_in[0];
    const void*  ei     = d_in[1];
    const void*  batch  = d_in[2];
    const float* w0     = (const float*)d_in[3];
    const float* b0     = (const float*)d_in[4];
    const float* ws     = (const float*)d_in[5];
    const float* bs     = (const float*)d_in[6];
    const float* gammas = (const float*)d_in[7];
    const float* betas  = (const float*)d_in[8];
    const float* wc1    = (const float*)d_in[9];
    const float* bc1    = (const float*)d_in[10];
    const float* wc2    = (const float*)d_in[11];
    const float* bc2    = (const float*)d_in[12];
    float* out = (float*)d_out;

    k_sniff<<<1, 256>>>((const int*)ei);
    k_zero<<<1024, 256>>>();
    k_deg<<<(Ee + 255) / 256, 256>>>(ei);
    k_scan1<<<NBLK, 1024>>>();
    k_scan2<<<1, 128>>>();
    k_scan3<<<NBLK, 1024>>>();
    k_fill<<<(Ee + 255) / 256, 256>>>(ei);

    const int gemm_grid = (Nn + 63) / 64;
    const int agg_grid  = (Nn + 3) / 4;
    for (int l = 0; l < 4; l++) {
        if (l == 0)
            k_gemm<<<gemm_grid, 256>>>(x, INF, INF, w0);
        else
            k_gemm<<<gemm_grid, 256>>>(nullptr, Hh, Hh, ws + (size_t)(l - 1) * Hh * Hh);
        const float* bias = (l == 0) ? b0 : bs + (size_t)(l - 1) * Hh;
        k_agg<<<agg_grid, 128>>>(bias, gammas + (size_t)l * Hh, betas + (size_t)l * Hh);
    }

    k_pool<<<(Nn + 127) / 128, 128>>>(batch);
    k_head<<<Gg, 64>>>(wc1, bc1, wc2, bc2, out);
}

// round 8
// speedup vs baseline: 1.2748x; 1.1360x over previous
#include <cuda_runtime.h>

// Problem constants
#define Nn   100000
#define Ee   800000
#define Gg   4096
#define INF  143
#define Hh   128
#define BN_INV 0.9999950000374997f   // rsqrt(1 + 1e-5)
#define NBLK ((Nn + 1023) / 1024)    // 98 scan blocks

// ---------------------------------------------------------------------------
// Device scratch (no allocations allowed in kernel_launch)
// ---------------------------------------------------------------------------
__device__ __align__(16) float g_h[Nn * Hh];     // g = dis * (h @ W), per layer
__device__ __align__(16) float g_act[Nn * Hh];   // post BN+ReLU activations
__device__ float g_dis[Nn];                      // deg^{-1/2}
__device__ int   g_deg[Nn];
__device__ int   g_rowptr[Nn + 1];
__device__ int   g_fill[Nn];
__device__ int   g_col[Ee];                      // src indices grouped by dst
__device__ __align__(16) float g_pool[Gg * Hh];
__device__ float g_cnt[Gg];
__device__ int   g_is64;                         // index dtype flag (1 = int64)
__device__ int   g_bsum[NBLK];                   // scan block sums

// ---------------------------------------------------------------------------
// TF32 helpers
// ---------------------------------------------------------------------------
__device__ __forceinline__ unsigned f2tf32(float x) {
    unsigned r;
    asm("cvt.rna.tf32.f32 %0, %1;" : "=r"(r) : "f"(x));
    return r;
}
__device__ __forceinline__ void mma_tf32(float* d, const unsigned* a,
                                         unsigned b0, unsigned b1) {
    asm volatile(
        "mma.sync.aligned.m16n8k8.row.col.f32.tf32.tf32.f32 "
        "{%0,%1,%2,%3}, {%4,%5,%6,%7}, {%8,%9}, {%0,%1,%2,%3};"
        : "+f"(d[0]), "+f"(d[1]), "+f"(d[2]), "+f"(d[3])
        : "r"(a[0]), "r"(a[1]), "r"(a[2]), "r"(a[3]), "r"(b0), "r"(b1));
}

// ---------------------------------------------------------------------------
// Dtype sniff: int64 little-endian values < 2^31 have zero high words at all
// odd 32-bit positions; int32 node indices are random so 256 odd words all
// zero is impossible in practice.
// ---------------------------------------------------------------------------
__global__ void k_sniff(const int* __restrict__ ei32) {
    __shared__ int ok;
    if (threadIdx.x == 0) ok = 1;
    __syncthreads();
    if (ei32[2 * threadIdx.x + 1] != 0) ok = 0;
    __syncthreads();
    if (threadIdx.x == 0) g_is64 = ok;
}

__device__ __forceinline__ int load_idx(const void* p, long long i) {
    return g_is64 ? (int)((const long long*)p)[i] : ((const int*)p)[i];
}

// ---------------------------------------------------------------------------
// Zero all per-call scratch
// ---------------------------------------------------------------------------
__global__ void k_zero() {
    int i = blockIdx.x * blockDim.x + threadIdx.x;
    int stride = gridDim.x * blockDim.x;
    for (int j = i; j < Nn; j += stride) { g_deg[j] = 0; g_fill[j] = 0; }
    for (int j = i; j < Gg * Hh; j += stride) g_pool[j] = 0.f;
    for (int j = i; j < Gg; j += stride) g_cnt[j] = 0.f;
}

// ---------------------------------------------------------------------------
// In-degree histogram over dst
// ---------------------------------------------------------------------------
__global__ void k_deg(const void* __restrict__ ei) {
    int e = blockIdx.x * blockDim.x + threadIdx.x;
    if (e < Ee) atomicAdd(&g_deg[load_idx(ei, (long long)Ee + e)], 1);
}

// ---------------------------------------------------------------------------
// Multi-block exclusive scan of g_deg -> g_rowptr (3 kernels)
// ---------------------------------------------------------------------------
__global__ __launch_bounds__(1024) void k_scan1() {   // block sums
    __shared__ int wsum[32];
    int i = blockIdx.x * 1024 + threadIdx.x;
    int lane = threadIdx.x & 31, wid = threadIdx.x >> 5;
    int v = (i < Nn) ? g_deg[i] : 0;
    #pragma unroll
    for (int o = 16; o; o >>= 1) v += __shfl_down_sync(0xFFFFFFFFu, v, o);
    if (lane == 0) wsum[wid] = v;
    __syncthreads();
    if (wid == 0) {
        int s = wsum[lane];
        #pragma unroll
        for (int o = 16; o; o >>= 1) s += __shfl_down_sync(0xFFFFFFFFu, s, o);
        if (lane == 0) g_bsum[blockIdx.x] = s;
    }
}

__global__ __launch_bounds__(128) void k_scan2() {    // scan 98 block sums
    __shared__ int wsum[4];
    int tid = threadIdx.x, lane = tid & 31, wid = tid >> 5;
    int v = (tid < NBLK) ? g_bsum[tid] : 0;
    int incl = v;
    #pragma unroll
    for (int o = 1; o < 32; o <<= 1) {
        int t = __shfl_up_sync(0xFFFFFFFFu, incl, o);
        if (lane >= o) incl += t;
    }
    if (lane == 31) wsum[wid] = incl;
    __syncthreads();
    int off = 0;
    #pragma unroll
    for (int w = 0; w < 4; w++) if (w < wid) off += wsum[w];
    if (tid < NBLK) g_bsum[tid] = off + incl - v;     // exclusive
    if (tid == 0) g_rowptr[Nn] = Ee;
}

__global__ __launch_bounds__(1024) void k_scan3() {   // local scan + offset
    __shared__ int wsum[32];
    int i = blockIdx.x * 1024 + threadIdx.x;
    int lane = threadIdx.x & 31, wid = threadIdx.x >> 5;
    int v = (i < Nn) ? g_deg[i] : 0;
    int incl = v;
    #pragma unroll
    for (int o = 1; o < 32; o <<= 1) {
        int t = __shfl_up_sync(0xFFFFFFFFu, incl, o);
        if (lane >= o) incl += t;
    }
    if (lane == 31) wsum[wid] = incl;
    __syncthreads();
    if (wid == 0) {
        int w = wsum[lane];
        int winc = w;
        #pragma unroll
        for (int o = 1; o < 32; o <<= 1) {
            int t = __shfl_up_sync(0xFFFFFFFFu, winc, o);
            if (lane >= o) winc += t;
        }
        wsum[lane] = winc - w;
    }
    __syncthreads();
    if (i < Nn) {
        g_rowptr[i] = g_bsum[blockIdx.x] + wsum[wid] + (incl - v);
        g_dis[i] = rsqrtf((float)v + 1.0f);
    }
}

// ---------------------------------------------------------------------------
// Scatter edges into CSR slots
// ---------------------------------------------------------------------------
__global__ void k_fill(const void* __restrict__ ei) {
    int e = blockIdx.x * blockDim.x + threadIdx.x;
    if (e < Ee) {
        int s = load_idx(ei, e);
        int d = load_idx(ei, (long long)Ee + e);
        int pos = g_rowptr[d] + atomicAdd(&g_fill[d], 1);
        g_col[pos] = s;
    }
}

// ---------------------------------------------------------------------------
// Tensor-core GEMM (3xTF32 split, full fp32-equivalent accuracy):
//   g_h[row,:] = dis[row] * (in[row,:] @ W), W is [K,128] row-major.
// Block tile 64x128, 8 warps = 4(M) x 2(N); warp tile 16x64 via 8x
// m16n8k8 fragments. KC=32 smem staging. B pre-split hi/lo in smem,
// A split in-register. in == nullptr means "read g_act".
// ---------------------------------------------------------------------------
#define KC 32
__global__ __launch_bounds__(256) void k_gemm(const float* __restrict__ in,
                                              int lda, int K,
                                              const float* __restrict__ W) {
    __shared__ float    sA[64 * 36];       // [m][k], stride 36 (conflict-free)
    __shared__ unsigned sBh[KC * 136];     // [k][n], stride 136 (conflict-free)
    __shared__ unsigned sBl[KC * 136];
    const float* src = in ? in : g_act;

    int tid  = threadIdx.x;
    int warp = tid >> 5, lane = tid & 31;
    int gid  = lane >> 2, tig = lane & 3;
    int wm   = warp >> 1, wn = warp & 1;
    int m0   = blockIdx.x * 64;
    int mw   = m0 + wm * 16;
    int n0w  = wn * 64;

    float acc[8][4];
    #pragma unroll
    for (int f = 0; f < 8; f++)
        #pragma unroll
        for (int j = 0; j < 4; j++) acc[f][j] = 0.f;

    for (int k0 = 0; k0 < K; k0 += KC) {
        // stage A tile (64 x 32 f32)
        #pragma unroll
        for (int t = 0; t < 8; t++) {
            int e = t * 256 + tid;
            int m = e >> 5, kk = e & 31;
            int row = m0 + m, kg = k0 + kk;
            sA[m * 36 + kk] = (row < Nn && kg < K) ? src[(long long)row * lda + kg] : 0.f;
        }
        // stage B tile (32 x 128), pre-split into tf32 hi/lo
        #pragma unroll
        for (int t = 0; t < 16; t++) {
            int e = t * 256 + tid;
            int kk = e >> 7, n = e & 127;
            int kg = k0 + kk;
            float v = (kg < K) ? W[kg * 128 + n] : 0.f;
            unsigned h = f2tf32(v);
            float lo = v - __uint_as_float(h);
            sBh[kk * 136 + n] = h;
            sBl[kk * 136 + n] = f2tf32(lo);
        }
        __syncthreads();

        #pragma unroll
        for (int ks = 0; ks < KC / 8; ks++) {
            int kb = ks * 8;
            // A fragment (rows mw+gid, mw+gid+8; cols kb+tig, kb+tig+4)
            float a0 = sA[(wm * 16 + gid) * 36 + kb + tig];
            float a1 = sA[(wm * 16 + gid + 8) * 36 + kb + tig];
            float a2 = sA[(wm * 16 + gid) * 36 + kb + tig + 4];
            float a3 = sA[(wm * 16 + gid + 8) * 36 + kb + tig + 4];
            unsigned ah[4] = { f2tf32(a0), f2tf32(a1), f2tf32(a2), f2tf32(a3) };
            unsigned al[4] = {
                f2tf32(a0 - __uint_as_float(ah[0])),
                f2tf32(a1 - __uint_as_float(ah[1])),
                f2tf32(a2 - __uint_as_float(ah[2])),
                f2tf32(a3 - __uint_as_float(ah[3])) };

            #pragma unroll
            for (int nf = 0; nf < 8; nf++) {
                int nb = n0w + nf * 8 + gid;
                unsigned bh0 = sBh[(kb + tig) * 136 + nb];
                unsigned bh1 = sBh[(kb + tig + 4) * 136 + nb];
                unsigned bl0 = sBl[(kb + tig) * 136 + nb];
                unsigned bl1 = sBl[(kb + tig + 4) * 136 + nb];
                mma_tf32(acc[nf], ah, bh0, bh1);   // hi*hi
                mma_tf32(acc[nf], al, bh0, bh1);   // lo*hi
                mma_tf32(acc[nf], ah, bl0, bl1);   // hi*lo
            }
        }
        __syncthreads();
    }

    // epilogue: scale by dis[row], write g_h
    int r0 = mw + gid, r1 = mw + gid + 8;
    float s0 = (r0 < Nn) ? g_dis[r0] : 0.f;
    float s1 = (r1 < Nn) ? g_dis[r1] : 0.f;
    #pragma unroll
    for (int nf = 0; nf < 8; nf++) {
        int c = n0w + nf * 8 + tig * 2;
        if (r0 < Nn) {
            float2 o = make_float2(acc[nf][0] * s0, acc[nf][1] * s0);
            *reinterpret_cast<float2*>(&g_h[(long long)r0 * Hh + c]) = o;
        }
        if (r1 < Nn) {
            float2 o = make_float2(acc[nf][2] * s1, acc[nf][3] * s1);
            *reinterpret_cast<float2*>(&g_h[(long long)r1 * Hh + c]) = o;
        }
    }
}

// ---------------------------------------------------------------------------
// Aggregation + bias + BN(eval) + ReLU (one warp per node, float4 per lane)
// ---------------------------------------------------------------------------
__global__ __launch_bounds__(128) void k_agg(const float* __restrict__ bias,
                                             const float* __restrict__ gamma,
                                             const float* __restrict__ beta) {
    int warp = threadIdx.x >> 5, lane = threadIdx.x & 31;
    int node = blockIdx.x * 4 + warp;
    if (node >= Nn) return;

    const float4* h4 = reinterpret_cast<const float4*>(g_h);
    int r0 = g_rowptr[node], r1 = g_rowptr[node + 1];

    float4 a = h4[(long long)node * 32 + lane];   // self term (dis-prescaled)
    int e = r0;
    for (; e + 4 <= r1; e += 4) {
        int s0 = g_col[e], s1 = g_col[e + 1], s2 = g_col[e + 2], s3 = g_col[e + 3];
        float4 v0 = h4[(long long)s0 * 32 + lane];
        float4 v1 = h4[(long long)s1 * 32 + lane];
        float4 v2 = h4[(long long)s2 * 32 + lane];
        float4 v3 = h4[(long long)s3 * 32 + lane];
        a.x += (v0.x + v1.x) + (v2.x + v3.x);
        a.y += (v0.y + v1.y) + (v2.y + v3.y);
        a.z += (v0.z + v1.z) + (v2.z + v3.z);
        a.w += (v0.w + v1.w) + (v2.w + v3.w);
    }
    for (; e < r1; e++) {
        float4 v = h4[(long long)g_col[e] * 32 + lane];
        a.x += v.x; a.y += v.y; a.z += v.z; a.w += v.w;
    }

    float d = g_dis[node];
    float4 bb = reinterpret_cast<const float4*>(bias)[lane];
    float4 gm = reinterpret_cast<const float4*>(gamma)[lane];
    float4 bt = reinterpret_cast<const float4*>(beta)[lane];
    float4 o;
    o.x = fmaxf(fmaf(gm.x * BN_INV, fmaf(d, a.x, bb.x), bt.x), 0.f);
    o.y = fmaxf(fmaf(gm.y * BN_INV, fmaf(d, a.y, bb.y), bt.y), 0.f);
    o.z = fmaxf(fmaf(gm.z * BN_INV, fmaf(d, a.z, bb.z), bt.z), 0.f);
    o.w = fmaxf(fmaf(gm.w * BN_INV, fmaf(d, a.w, bb.w), bt.w), 0.f);
    reinterpret_cast<float4*>(g_act)[(long long)node * 32 + lane] = o;
}

// ---------------------------------------------------------------------------
// Global mean pool, segmented: batch is sorted, so a warp walks 32 consecutive
// node rows accumulating in registers and flushes atomics on graph change.
// ---------------------------------------------------------------------------
__global__ __launch_bounds__(128) void k_pool(const void* __restrict__ batch) {
    int warp = threadIdx.x >> 5, lane = threadIdx.x & 31;
    int base = (blockIdx.x * 4 + warp) * 32;
    if (base >= Nn) return;
    int end = base + 32 < Nn ? base + 32 : Nn;

    const float4* a4 = reinterpret_cast<const float4*>(g_act);
    float4 acc = make_float4(0.f, 0.f, 0.f, 0.f);
    int cur = load_idx(batch, base);
    int cnt = 0;

    for (int n = base; n < end; n++) {
        int g = load_idx(batch, n);
        if (g != cur) {
            float* dst = &g_pool[cur * Hh + lane * 4];
            atomicAdd(dst + 0, acc.x); atomicAdd(dst + 1, acc.y);
            atomicAdd(dst + 2, acc.z); atomicAdd(dst + 3, acc.w);
            if (lane == 0) atomicAdd(&g_cnt[cur], (float)cnt);
            acc = make_float4(0.f, 0.f, 0.f, 0.f);
            cnt = 0; cur = g;
        }
        float4 v = a4[(long long)n * 32 + lane];
        acc.x += v.x; acc.y += v.y; acc.z += v.z; acc.w += v.w;
        cnt++;
    }
    float* dst = &g_pool[cur * Hh + lane * 4];
    atomicAdd(dst + 0, acc.x); atomicAdd(dst + 1, acc.y);
    atomicAdd(dst + 2, acc.z); atomicAdd(dst + 3, acc.w);
    if (lane == 0) atomicAdd(&g_cnt[cur], (float)cnt);
}

// ---------------------------------------------------------------------------
// Head: mean -> relu(mean@wc1 + bc1) -> @wc2 + bc2. One 64-thread block/graph.
// ---------------------------------------------------------------------------
__global__ __launch_bounds__(64) void k_head(const float* __restrict__ wc1,
                                             const float* __restrict__ bc1,
                                             const float* __restrict__ wc2,
                                             const float* __restrict__ bc2,
                                             float* __restrict__ out) {
    __shared__ float mean[128];
    __shared__ float part[2];
    int g = blockIdx.x, t = threadIdx.x;
    float inv = 1.f / fmaxf(g_cnt[g], 1.f);
    mean[t]      = g_pool[g * Hh + t] * inv;
    mean[t + 64] = g_pool[g * Hh + 64 + t] * inv;
    __syncthreads();

    float z = bc1[t];
    #pragma unroll 8
    for (int k = 0; k < 128; k++)
        z = fmaf(mean[k], wc1[k * 64 + t], z);
    z = fmaxf(z, 0.f) * wc2[t];

    #pragma unroll
    for (int o = 16; o; o >>= 1) z += __shfl_down_sync(0xFFFFFFFFu, z, o);
    if ((t & 31) == 0) part[t >> 5] = z;
    __syncthreads();
    if (t == 0) out[g] = part[0] + part[1] + bc2[0];
}

// ---------------------------------------------------------------------------
// Launch
// ---------------------------------------------------------------------------
extern "C" void kernel_launch(void* const* d_in, const int* in_sizes, int n_in,
                              void* d_out, int out_size) {
    const float* x      = (const float*)d_in[0];
    const void*  ei     = d_in[1];
    const void*  batch  = d_in[2];
    const float* w0     = (const float*)d_in[3];
    const float* b0     = (const float*)d_in[4];
    const float* ws     = (const float*)d_in[5];
    const float* bs     = (const float*)d_in[6];
    const float* gammas = (const float*)d_in[7];
    const float* betas  = (const float*)d_in[8];
    const float* wc1    = (const float*)d_in[9];
    const float* bc1    = (const float*)d_in[10];
    const float* wc2    = (const float*)d_in[11];
    const float* bc2    = (const float*)d_in[12];
    float* out = (float*)d_out;

    k_sniff<<<1, 256>>>((const int*)ei);
    k_zero<<<1024, 256>>>();
    k_deg<<<(Ee + 255) / 256, 256>>>(ei);
    k_scan1<<<NBLK, 1024>>>();
    k_scan2<<<1, 128>>>();
    k_scan3<<<NBLK, 1024>>>();
    k_fill<<<(Ee + 255) / 256, 256>>>(ei);

    const int gemm_grid = (Nn + 63) / 64;
    const int agg_grid  = (Nn + 3) / 4;
    for (int l = 0; l < 4; l++) {
        if (l == 0)
            k_gemm<<<gemm_grid, 256>>>(x, INF, INF, w0);
        else
            k_gemm<<<gemm_grid, 256>>>(nullptr, Hh, Hh, ws + (size_t)(l - 1) * Hh * Hh);
        const float* bias = (l == 0) ? b0 : bs + (size_t)(l - 1) * Hh;
        k_agg<<<agg_grid, 128>>>(bias, gammas + (size_t)l * Hh, betas + (size_t)l * Hh);
    }

    k_pool<<<(Nn + 127) / 128, 128>>>(batch);
    k_head<<<Gg, 64>>>(wc1, bc1, wc2, bc2, out);
}